// round 2
// baseline (speedup 1.0000x reference)
#include <cuda_runtime.h>
#include <cuda_bf16.h>

// Problem constants (fixed shapes for this problem)
#define NN 40000
#define DD 128
#define EE 640000

// Scratch (device globals; no allocation allowed)
__device__ float g_y[NN * DD];        // relu(x @ W^T + b) per node, 20.5 MB (L2-resident)
__device__ int   g_deg[NN];
__device__ int   g_off[NN];
__device__ int   g_cur[NN];
__device__ int   g_csr[EE];

// ---------------------------------------------------------------------------
// Kernel 1: zero degree counters
// ---------------------------------------------------------------------------
__global__ void k_zero_deg(int n) {
    int i = blockIdx.x * blockDim.x + threadIdx.x;
    if (i < n) g_deg[i] = 0;
}

// ---------------------------------------------------------------------------
// Kernel 2: y = relu(x @ W^T + b)  (N x D) @ (D x D)
// Block: 256 threads, computes 64 rows x 128 cols. k-chunked smem tiling.
// ---------------------------------------------------------------------------
__global__ __launch_bounds__(256) void k_gemm_relu(
    const float* __restrict__ x, const float* __restrict__ W,
    const float* __restrict__ b, int nrows)
{
    __shared__ float xs[64][32];     // x tile  (writes: lane=kk -> conflict-free)
    __shared__ float wt[32][132];    // W^T tile, padded stride 132 (16B-aligned rows)

    const int t    = threadIdx.x;
    const int row0 = blockIdx.x * 64;
    const int ty   = t >> 5;         // 0..7  -> 8 rows each
    const int tx   = t & 31;         // 0..31 -> 4 cols each

    float acc[8][4];
#pragma unroll
    for (int r = 0; r < 8; r++)
#pragma unroll
        for (int c = 0; c < 4; c++) acc[r][c] = 0.f;

    for (int kc = 0; kc < DD; kc += 32) {
        // load x tile: 64x32
#pragma unroll
        for (int i = t; i < 64 * 32; i += 256) {
            int r = i >> 5, kk = i & 31;
            int row = row0 + r;
            xs[r][kk] = (row < nrows) ? x[row * DD + kc + kk] : 0.f;
        }
        // load W tile transposed: wt[kk][c] = W[c][kc+kk] (coalesced gmem reads)
#pragma unroll
        for (int i = t; i < 128 * 32; i += 256) {
            int c = i >> 5, kk = i & 31;
            wt[kk][c] = W[c * DD + kc + kk];
        }
        __syncthreads();

#pragma unroll
        for (int kk = 0; kk < 32; kk++) {
            float4 wv = *(const float4*)&wt[kk][tx * 4];  // conflict-free LDS.128
            float xv[8];
#pragma unroll
            for (int r = 0; r < 8; r++) xv[r] = xs[ty * 8 + r][kk];  // broadcast
#pragma unroll
            for (int r = 0; r < 8; r++) {
                acc[r][0] = fmaf(xv[r], wv.x, acc[r][0]);
                acc[r][1] = fmaf(xv[r], wv.y, acc[r][1]);
                acc[r][2] = fmaf(xv[r], wv.z, acc[r][2]);
                acc[r][3] = fmaf(xv[r], wv.w, acc[r][3]);
            }
        }
        __syncthreads();
    }

    float4 bv = *(const float4*)&b[tx * 4];
#pragma unroll
    for (int r = 0; r < 8; r++) {
        int row = row0 + ty * 8 + r;
        if (row < nrows) {
            float4 o;
            o.x = fmaxf(acc[r][0] + bv.x, 0.f);
            o.y = fmaxf(acc[r][1] + bv.y, 0.f);
            o.z = fmaxf(acc[r][2] + bv.z, 0.f);
            o.w = fmaxf(acc[r][3] + bv.w, 0.f);
            *(float4*)&g_y[row * DD + tx * 4] = o;
        }
    }
}

// ---------------------------------------------------------------------------
// Kernel 3: histogram of dst degrees
// ---------------------------------------------------------------------------
__global__ void k_hist(const int* __restrict__ e, int ne) {
    int i = blockIdx.x * blockDim.x + threadIdx.x;
    if (i < ne) atomicAdd(&g_deg[e[2 * i + 1]], 1);
}

// ---------------------------------------------------------------------------
// Kernel 4: exclusive prefix scan over deg -> off, cur  (single block, 1024 thr)
// ---------------------------------------------------------------------------
__global__ __launch_bounds__(1024) void k_scan(int n) {
    __shared__ int warpsum[32];
    __shared__ int carry;
    const int t = threadIdx.x;
    const int lane = t & 31, wid = t >> 5;
    if (t == 0) carry = 0;
    __syncthreads();

    const int nRound = ((n + 1023) / 1024) * 1024;
    for (int base = 0; base < nRound; base += 1024) {
        int i = base + t;
        int v = (i < n) ? g_deg[i] : 0;
        // warp inclusive scan
        int s = v;
#pragma unroll
        for (int d = 1; d < 32; d <<= 1) {
            int m = __shfl_up_sync(0xFFFFFFFFu, s, d);
            if (lane >= d) s += m;
        }
        if (lane == 31) warpsum[wid] = s;
        __syncthreads();
        if (t < 32) {
            int ws = warpsum[t];
            int ss = ws;
#pragma unroll
            for (int d = 1; d < 32; d <<= 1) {
                int m = __shfl_up_sync(0xFFFFFFFFu, ss, d);
                if (t >= d) ss += m;
            }
            warpsum[t] = ss - ws;  // exclusive warp offsets
        }
        __syncthreads();
        int excl = s - v + warpsum[wid] + carry;
        if (i < n) { g_off[i] = excl; g_cur[i] = excl; }
        __syncthreads();
        if (t == 1023) carry = excl + v;
        __syncthreads();
    }
}

// ---------------------------------------------------------------------------
// Kernel 5: scatter edges into dst-CSR
// ---------------------------------------------------------------------------
__global__ void k_scatter(const int* __restrict__ e, int ne) {
    int i = blockIdx.x * blockDim.x + threadIdx.x;
    if (i < ne) {
        int d = e[2 * i + 1];
        int p = atomicAdd(&g_cur[d], 1);
        g_csr[p] = e[2 * i];  // src
    }
}

// ---------------------------------------------------------------------------
// Kernel 6: per-dst gather-max over y + residual + RMSNorm.  One warp / node.
// ---------------------------------------------------------------------------
__global__ __launch_bounds__(256) void k_aggregate(
    const float* __restrict__ x, const float* __restrict__ g,
    const float* __restrict__ rb, float* __restrict__ out, int n)
{
    const int node = (blockIdx.x * blockDim.x + threadIdx.x) >> 5;
    const int lane = threadIdx.x & 31;
    if (node >= n) return;

    const int start = g_off[node];
    const int cnt   = g_deg[node];
    const float4* yv = (const float4*)g_y;

    float4 agg = make_float4(0.f, 0.f, 0.f, 0.f);
    int j = 0;
    // unrolled-by-4 for memory-level parallelism
    for (; j + 4 <= cnt; j += 4) {
        int s0 = g_csr[start + j];
        int s1 = g_csr[start + j + 1];
        int s2 = g_csr[start + j + 2];
        int s3 = g_csr[start + j + 3];
        float4 v0 = yv[s0 * 32 + lane];
        float4 v1 = yv[s1 * 32 + lane];
        float4 v2 = yv[s2 * 32 + lane];
        float4 v3 = yv[s3 * 32 + lane];
        agg.x = fmaxf(agg.x, fmaxf(fmaxf(v0.x, v1.x), fmaxf(v2.x, v3.x)));
        agg.y = fmaxf(agg.y, fmaxf(fmaxf(v0.y, v1.y), fmaxf(v2.y, v3.y)));
        agg.z = fmaxf(agg.z, fmaxf(fmaxf(v0.z, v1.z), fmaxf(v2.z, v3.z)));
        agg.w = fmaxf(agg.w, fmaxf(fmaxf(v0.w, v1.w), fmaxf(v2.w, v3.w)));
    }
    for (; j < cnt; j++) {
        int s = g_csr[start + j];
        float4 v = yv[s * 32 + lane];
        agg.x = fmaxf(agg.x, v.x);
        agg.y = fmaxf(agg.y, v.y);
        agg.z = fmaxf(agg.z, v.z);
        agg.w = fmaxf(agg.w, v.w);
    }

    float4 xv = ((const float4*)x)[node * 32 + lane];
    float4 h;
    h.x = xv.x + agg.x; h.y = xv.y + agg.y;
    h.z = xv.z + agg.z; h.w = xv.w + agg.w;

    float ss = h.x * h.x + h.y * h.y + h.z * h.z + h.w * h.w;
#pragma unroll
    for (int d = 16; d; d >>= 1) ss += __shfl_xor_sync(0xFFFFFFFFu, ss, d);

    float inv = rsqrtf(ss * (1.0f / DD) + 1e-5f);

    float4 gv = ((const float4*)g)[lane];
    float4 rv = ((const float4*)rb)[lane];
    float4 o;
    o.x = h.x * inv * gv.x + rv.x;
    o.y = h.y * inv * gv.y + rv.y;
    o.z = h.z * inv * gv.z + rv.z;
    o.w = h.w * inv * gv.w + rv.w;
    ((float4*)out)[node * 32 + lane] = o;
}

// ---------------------------------------------------------------------------
// Launch
// ---------------------------------------------------------------------------
extern "C" void kernel_launch(void* const* d_in, const int* in_sizes, int n_in,
                              void* d_out, int out_size)
{
    const float* x  = (const float*)d_in[0];
    const int*   e  = (const int*)  d_in[1];
    const float* W  = (const float*)d_in[2];
    const float* b  = (const float*)d_in[3];
    const float* g  = (const float*)d_in[4];
    const float* rb = (const float*)d_in[5];
    float* out = (float*)d_out;

    const int n  = in_sizes[0] / DD;   // 40000
    const int ne = in_sizes[1] / 2;    // 640000

    k_zero_deg<<<(n + 255) / 256, 256>>>(n);
    k_gemm_relu<<<(n + 63) / 64, 256>>>(x, W, b, n);
    k_hist<<<(ne + 255) / 256, 256>>>(e, ne);
    k_scan<<<1, 1024>>>(n);
    k_scatter<<<(ne + 255) / 256, 256>>>(e, ne);
    k_aggregate<<<(n * 32 + 255) / 256, 256>>>(x, g, rb, out, n);
}

// round 3
// speedup vs baseline: 1.9249x; 1.9249x over previous
#include <cuda_runtime.h>
#include <cuda_bf16.h>

// Problem constants (fixed shapes for this problem)
#define NN 40000
#define DD 128
#define EE 640000

// Scratch (device globals; no allocation allowed)
__device__ float g_y[NN * DD];        // relu(x @ W^T + b) per node, 20.5 MB (L2-resident)
__device__ int   g_deg[NN];
__device__ int   g_off[NN];
__device__ int   g_cur[NN];
__device__ int   g_csr[EE];
__device__ int   g_total;             // global CSR cursor

// ---------------------------------------------------------------------------
// Kernel 1: zero degree counters + cursor
// ---------------------------------------------------------------------------
__global__ void k_zero_deg(int n) {
    int i = blockIdx.x * blockDim.x + threadIdx.x;
    if (i < n) g_deg[i] = 0;
    if (i == 0) g_total = 0;
}

// ---------------------------------------------------------------------------
// Kernel 2: y = relu(x @ W^T + b)  (N x D) @ (D x D)
// Block: 256 threads, computes 64 rows x 128 cols. k-chunked smem tiling.
// N is an exact multiple of 64 (40000 = 625*64) -> no bounds checks.
// ---------------------------------------------------------------------------
__global__ __launch_bounds__(256) void k_gemm_relu(
    const float* __restrict__ x, const float* __restrict__ W,
    const float* __restrict__ b)
{
    __shared__ float xs[64][32];     // x tile  (writes: lane=kk -> conflict-free)
    __shared__ float wt[32][132];    // W^T tile, padded stride 132 (16B-aligned rows)

    const int t    = threadIdx.x;
    const int row0 = blockIdx.x * 64;
    const int ty   = t >> 5;         // 0..7  -> 8 rows each
    const int tx   = t & 31;         // 0..31 -> 4 cols each

    float acc[8][4];
#pragma unroll
    for (int r = 0; r < 8; r++)
#pragma unroll
        for (int c = 0; c < 4; c++) acc[r][c] = 0.f;

    for (int kc = 0; kc < DD; kc += 32) {
        // load x tile: 64x32
#pragma unroll
        for (int i = t; i < 64 * 32; i += 256) {
            int r = i >> 5, kk = i & 31;
            xs[r][kk] = x[(row0 + r) * DD + kc + kk];
        }
        // load W tile transposed: wt[kk][c] = W[c][kc+kk] (coalesced gmem reads)
#pragma unroll
        for (int i = t; i < 128 * 32; i += 256) {
            int c = i >> 5, kk = i & 31;
            wt[kk][c] = W[c * DD + kc + kk];
        }
        __syncthreads();

#pragma unroll
        for (int kk = 0; kk < 32; kk++) {
            float4 wv = *(const float4*)&wt[kk][tx * 4];  // conflict-free LDS.128
            float xv[8];
#pragma unroll
            for (int r = 0; r < 8; r++) xv[r] = xs[ty * 8 + r][kk];  // broadcast
#pragma unroll
            for (int r = 0; r < 8; r++) {
                acc[r][0] = fmaf(xv[r], wv.x, acc[r][0]);
                acc[r][1] = fmaf(xv[r], wv.y, acc[r][1]);
                acc[r][2] = fmaf(xv[r], wv.z, acc[r][2]);
                acc[r][3] = fmaf(xv[r], wv.w, acc[r][3]);
            }
        }
        __syncthreads();
    }

    float4 bv = *(const float4*)&b[tx * 4];
#pragma unroll
    for (int r = 0; r < 8; r++) {
        int row = row0 + ty * 8 + r;
        float4 o;
        o.x = fmaxf(acc[r][0] + bv.x, 0.f);
        o.y = fmaxf(acc[r][1] + bv.y, 0.f);
        o.z = fmaxf(acc[r][2] + bv.z, 0.f);
        o.w = fmaxf(acc[r][3] + bv.w, 0.f);
        *(float4*)&g_y[row * DD + tx * 4] = o;
    }
}

// ---------------------------------------------------------------------------
// Kernel 3: histogram of dst degrees (coalesced int2 edge loads)
// ---------------------------------------------------------------------------
__global__ void k_hist(const int2* __restrict__ e, int ne) {
    int i = blockIdx.x * blockDim.x + threadIdx.x;
    if (i < ne) {
        int2 p = e[i];
        atomicAdd(&g_deg[p.y], 1);
    }
}

// ---------------------------------------------------------------------------
// Kernel 4: offsets via block scan + atomic block base.
// CSR segment ORDER is nondeterministic across blocks, but segment-max is
// order-invariant, so the final output is deterministic.
// ---------------------------------------------------------------------------
__global__ __launch_bounds__(256) void k_off(int n) {
    __shared__ int wsum[8];
    __shared__ int blockbase;
    const int t    = threadIdx.x;
    const int lane = t & 31, wid = t >> 5;
    const int i    = blockIdx.x * 256 + t;

    int v = (i < n) ? g_deg[i] : 0;

    // warp inclusive scan
    int s = v;
#pragma unroll
    for (int d = 1; d < 32; d <<= 1) {
        int m = __shfl_up_sync(0xFFFFFFFFu, s, d);
        if (lane >= d) s += m;
    }
    if (lane == 31) wsum[wid] = s;
    __syncthreads();

    if (t < 8) {
        int ws = wsum[t];
        int ss = ws;
#pragma unroll
        for (int d = 1; d < 8; d <<= 1) {
            int m = __shfl_up_sync(0xFFu, ss, d);
            if (t >= d) ss += m;
        }
        wsum[t] = ss - ws;               // exclusive warp offsets
        if (t == 7) {                    // ss is block total here
            blockbase = atomicAdd(&g_total, ss);
        }
    }
    __syncthreads();

    if (i < n) {
        int excl = blockbase + wsum[wid] + (s - v);
        g_off[i] = excl;
        g_cur[i] = excl;
    }
}

// ---------------------------------------------------------------------------
// Kernel 5: scatter edges into dst-CSR (coalesced int2 edge loads)
// ---------------------------------------------------------------------------
__global__ void k_scatter(const int2* __restrict__ e, int ne) {
    int i = blockIdx.x * blockDim.x + threadIdx.x;
    if (i < ne) {
        int2 p = e[i];
        int pos = atomicAdd(&g_cur[p.y], 1);
        g_csr[pos] = p.x;  // src
    }
}

// ---------------------------------------------------------------------------
// Kernel 6: per-dst gather-max over y + residual + RMSNorm.  One warp / node.
// ---------------------------------------------------------------------------
__global__ __launch_bounds__(256) void k_aggregate(
    const float* __restrict__ x, const float* __restrict__ g,
    const float* __restrict__ rb, float* __restrict__ out, int n)
{
    const int node = (blockIdx.x * blockDim.x + threadIdx.x) >> 5;
    const int lane = threadIdx.x & 31;
    if (node >= n) return;

    const int start = g_off[node];
    const int cnt   = g_deg[node];
    const float4* yv = (const float4*)g_y;

    float4 agg = make_float4(0.f, 0.f, 0.f, 0.f);
    int j = 0;
    // unrolled-by-4 for memory-level parallelism
    for (; j + 4 <= cnt; j += 4) {
        int s0 = g_csr[start + j];
        int s1 = g_csr[start + j + 1];
        int s2 = g_csr[start + j + 2];
        int s3 = g_csr[start + j + 3];
        float4 v0 = yv[s0 * 32 + lane];
        float4 v1 = yv[s1 * 32 + lane];
        float4 v2 = yv[s2 * 32 + lane];
        float4 v3 = yv[s3 * 32 + lane];
        agg.x = fmaxf(agg.x, fmaxf(fmaxf(v0.x, v1.x), fmaxf(v2.x, v3.x)));
        agg.y = fmaxf(agg.y, fmaxf(fmaxf(v0.y, v1.y), fmaxf(v2.y, v3.y)));
        agg.z = fmaxf(agg.z, fmaxf(fmaxf(v0.z, v1.z), fmaxf(v2.z, v3.z)));
        agg.w = fmaxf(agg.w, fmaxf(fmaxf(v0.w, v1.w), fmaxf(v2.w, v3.w)));
    }
    for (; j < cnt; j++) {
        int s = g_csr[start + j];
        float4 v = yv[s * 32 + lane];
        agg.x = fmaxf(agg.x, v.x);
        agg.y = fmaxf(agg.y, v.y);
        agg.z = fmaxf(agg.z, v.z);
        agg.w = fmaxf(agg.w, v.w);
    }

    float4 xv = ((const float4*)x)[node * 32 + lane];
    float4 h;
    h.x = xv.x + agg.x; h.y = xv.y + agg.y;
    h.z = xv.z + agg.z; h.w = xv.w + agg.w;

    float ss = h.x * h.x + h.y * h.y + h.z * h.z + h.w * h.w;
#pragma unroll
    for (int d = 16; d; d >>= 1) ss += __shfl_xor_sync(0xFFFFFFFFu, ss, d);

    float inv = rsqrtf(ss * (1.0f / DD) + 1e-5f);

    float4 gv = ((const float4*)g)[lane];
    float4 rv = ((const float4*)rb)[lane];
    float4 o;
    o.x = h.x * inv * gv.x + rv.x;
    o.y = h.y * inv * gv.y + rv.y;
    o.z = h.z * inv * gv.z + rv.z;
    o.w = h.w * inv * gv.w + rv.w;
    ((float4*)out)[node * 32 + lane] = o;
}

// ---------------------------------------------------------------------------
// Launch
// ---------------------------------------------------------------------------
extern "C" void kernel_launch(void* const* d_in, const int* in_sizes, int n_in,
                              void* d_out, int out_size)
{
    const float* x  = (const float*)d_in[0];
    const int2*  e  = (const int2*) d_in[1];
    const float* W  = (const float*)d_in[2];
    const float* b  = (const float*)d_in[3];
    const float* g  = (const float*)d_in[4];
    const float* rb = (const float*)d_in[5];
    float* out = (float*)d_out;

    const int n  = in_sizes[0] / DD;   // 40000
    const int ne = in_sizes[1] / 2;    // 640000

    k_zero_deg<<<(n + 255) / 256, 256>>>(n);
    k_gemm_relu<<<n / 64, 256>>>(x, W, b);
    k_hist<<<(ne + 255) / 256, 256>>>(e, ne);
    k_off<<<(n + 255) / 256, 256>>>(n);
    k_scatter<<<(ne + 255) / 256, 256>>>(e, ne);
    k_aggregate<<<(n * 32 + 255) / 256, 256>>>(x, g, rb, out, n);
}

// round 5
// speedup vs baseline: 2.2163x; 1.1514x over previous
#include <cuda_runtime.h>
#include <cuda_fp16.h>
#include <cuda_bf16.h>

// Problem constants (fixed shapes for this problem)
#define NN 40000
#define DD 128
#define EE 640000

// Scratch (device globals; no allocation allowed)
__device__ __half g_y[NN * DD];       // relu(x @ W^T + b) per node, fp16: 10.2 MB (L2-resident)
__device__ int    g_deg[NN];
__device__ int    g_off[NN];
__device__ int    g_cur[NN];
__device__ int    g_csr[EE];
__device__ int    g_total;            // global CSR cursor

static __device__ __forceinline__ unsigned h2_bits(__half2 v) {
    return *reinterpret_cast<unsigned*>(&v);
}

// ---------------------------------------------------------------------------
// Kernel 1: zero degree counters + cursor
// ---------------------------------------------------------------------------
__global__ void k_zero_deg(int n) {
    int i = blockIdx.x * blockDim.x + threadIdx.x;
    if (i < n) g_deg[i] = 0;
    if (i == 0) g_total = 0;
}

// ---------------------------------------------------------------------------
// Kernel 2: y = relu(x @ W^T + b), output fp16.
// Packed f32x2 FFMA: each thread owns 4 row-pairs x 4 cols.
// Row pair (2r, 2r+1) lives in the two f32x2 halves; the W operand is
// duplicated into both halves (4 packs per kk, shared across all rows).
// N multiple of 64 (40000 = 625*64) -> no bounds checks.
// ---------------------------------------------------------------------------
__global__ __launch_bounds__(256) void k_gemm_relu(
    const float* __restrict__ x, const float* __restrict__ W,
    const float* __restrict__ b)
{
    __shared__ float xs[32][66];     // [kk][row], stride 66: aligned LDS.64 row-pairs
    __shared__ float wt[32][132];    // [kk][col], padded

    const int t    = threadIdx.x;
    const int row0 = blockIdx.x * 64;
    const int ty   = t >> 5;         // warp id 0..7 -> rows ty*8 .. ty*8+7
    const int tx   = t & 31;         // lane -> cols tx*4 .. tx*4+3

    unsigned long long acc[4][4];    // [row pair][col], f32x2 packed
#pragma unroll
    for (int r = 0; r < 4; r++)
#pragma unroll
        for (int c = 0; c < 4; c++) acc[r][c] = 0ull;

    for (int kc = 0; kc < DD; kc += 32) {
        // x tile: gmem coalesced (t -> consecutive kk)
#pragma unroll
        for (int i = t; i < 64 * 32; i += 256) {
            int r = i >> 5, kk = i & 31;
            xs[kk][r] = x[(row0 + r) * DD + kc + kk];
        }
        // W tile transposed: wt[kk][c] = W[c][kc+kk]
#pragma unroll
        for (int i = t; i < 128 * 32; i += 256) {
            int c = i >> 5, kk = i & 31;
            wt[kk][c] = W[c * DD + kc + kk];
        }
        __syncthreads();

#pragma unroll
        for (int kk = 0; kk < 32; kk++) {
            float4 wv = *(const float4*)&wt[kk][tx * 4];   // conflict-free LDS.128
            unsigned long long wd[4];
            asm("mov.b64 %0, {%1, %1};" : "=l"(wd[0]) : "f"(wv.x));
            asm("mov.b64 %0, {%1, %1};" : "=l"(wd[1]) : "f"(wv.y));
            asm("mov.b64 %0, {%1, %1};" : "=l"(wd[2]) : "f"(wv.z));
            asm("mov.b64 %0, {%1, %1};" : "=l"(wd[3]) : "f"(wv.w));

            unsigned long long xp[4];                      // row-pair broadcasts (LDS.64)
#pragma unroll
            for (int r = 0; r < 4; r++)
                xp[r] = *(const unsigned long long*)&xs[kk][ty * 8 + 2 * r];

#pragma unroll
            for (int r = 0; r < 4; r++)
#pragma unroll
                for (int c = 0; c < 4; c++)
                    asm("fma.rn.f32x2 %0, %1, %2, %0;"
                        : "+l"(acc[r][c]) : "l"(xp[r]), "l"(wd[c]));
        }
        __syncthreads();
    }

    float4 bv = *(const float4*)&b[tx * 4];
#pragma unroll
    for (int r = 0; r < 4; r++) {
        float lo[4], hi[4];
#pragma unroll
        for (int c = 0; c < 4; c++) {
            unsigned int l = (unsigned int)(acc[r][c] & 0xFFFFFFFFull);
            unsigned int h = (unsigned int)(acc[r][c] >> 32);
            lo[c] = __uint_as_float(l);
            hi[c] = __uint_as_float(h);
        }
        int rowA = row0 + ty * 8 + 2 * r;      // low half
        int rowB = rowA + 1;                   // high half
        float a0 = fmaxf(lo[0] + bv.x, 0.f), a1 = fmaxf(lo[1] + bv.y, 0.f);
        float a2 = fmaxf(lo[2] + bv.z, 0.f), a3 = fmaxf(lo[3] + bv.w, 0.f);
        float b0 = fmaxf(hi[0] + bv.x, 0.f), b1 = fmaxf(hi[1] + bv.y, 0.f);
        float b2 = fmaxf(hi[2] + bv.z, 0.f), b3 = fmaxf(hi[3] + bv.w, 0.f);

        uint2 pa, pb;
        pa.x = h2_bits(__floats2half2_rn(a0, a1));
        pa.y = h2_bits(__floats2half2_rn(a2, a3));
        pb.x = h2_bits(__floats2half2_rn(b0, b1));
        pb.y = h2_bits(__floats2half2_rn(b2, b3));
        *(uint2*)&g_y[rowA * DD + tx * 4] = pa;
        *(uint2*)&g_y[rowB * DD + tx * 4] = pb;
    }
}

// ---------------------------------------------------------------------------
// Kernel 3: histogram of dst degrees (coalesced int2 edge loads)
// ---------------------------------------------------------------------------
__global__ void k_hist(const int2* __restrict__ e, int ne) {
    int i = blockIdx.x * blockDim.x + threadIdx.x;
    if (i < ne) {
        int2 p = e[i];
        atomicAdd(&g_deg[p.y], 1);
    }
}

// ---------------------------------------------------------------------------
// Kernel 4: offsets via block scan + atomic block base.
// Segment order across blocks is nondeterministic; max is order-invariant.
// ---------------------------------------------------------------------------
__global__ __launch_bounds__(256) void k_off(int n) {
    __shared__ int wsum[8];
    __shared__ int blockbase;
    const int t    = threadIdx.x;
    const int lane = t & 31, wid = t >> 5;
    const int i    = blockIdx.x * 256 + t;

    int v = (i < n) ? g_deg[i] : 0;

    int s = v;
#pragma unroll
    for (int d = 1; d < 32; d <<= 1) {
        int m = __shfl_up_sync(0xFFFFFFFFu, s, d);
        if (lane >= d) s += m;
    }
    if (lane == 31) wsum[wid] = s;
    __syncthreads();

    if (t < 8) {
        int ws = wsum[t];
        int ss = ws;
#pragma unroll
        for (int d = 1; d < 8; d <<= 1) {
            int m = __shfl_up_sync(0xFFu, ss, d);
            if (t >= d) ss += m;
        }
        wsum[t] = ss - ws;
        if (t == 7) blockbase = atomicAdd(&g_total, ss);
    }
    __syncthreads();

    if (i < n) {
        int excl = blockbase + wsum[wid] + (s - v);
        g_off[i] = excl;
        g_cur[i] = excl;
    }
}

// ---------------------------------------------------------------------------
// Kernel 5: scatter edges into dst-CSR (coalesced int2 edge loads)
// ---------------------------------------------------------------------------
__global__ void k_scatter(const int2* __restrict__ e, int ne) {
    int i = blockIdx.x * blockDim.x + threadIdx.x;
    if (i < ne) {
        int2 p = e[i];
        int pos = atomicAdd(&g_cur[p.y], 1);
        g_csr[pos] = p.x;  // src
    }
}

// ---------------------------------------------------------------------------
// Kernel 6: per-dst gather-max over fp16 y + residual + RMSNorm. Warp/node.
// Each lane loads 8B (4 halves) per edge; half2 max; fp32 finish.
// ---------------------------------------------------------------------------
__global__ __launch_bounds__(256) void k_aggregate(
    const float* __restrict__ x, const float* __restrict__ g,
    const float* __restrict__ rb, float* __restrict__ out, int n)
{
    const int node = (blockIdx.x * blockDim.x + threadIdx.x) >> 5;
    const int lane = threadIdx.x & 31;
    if (node >= n) return;

    const int start = g_off[node];
    const int cnt   = g_deg[node];
    const uint2* yv = (const uint2*)g_y;   // 8B per lane per row

    __half2 m0 = __float2half2_rn(0.f);
    __half2 m1 = __float2half2_rn(0.f);

    int j = 0;
    for (; j + 4 <= cnt; j += 4) {
        int s0 = g_csr[start + j];
        int s1 = g_csr[start + j + 1];
        int s2 = g_csr[start + j + 2];
        int s3 = g_csr[start + j + 3];
        uint2 v0 = yv[s0 * 32 + lane];
        uint2 v1 = yv[s1 * 32 + lane];
        uint2 v2 = yv[s2 * 32 + lane];
        uint2 v3 = yv[s3 * 32 + lane];
        m0 = __hmax2(m0, __hmax2(__hmax2(*(__half2*)&v0.x, *(__half2*)&v1.x),
                                 __hmax2(*(__half2*)&v2.x, *(__half2*)&v3.x)));
        m1 = __hmax2(m1, __hmax2(__hmax2(*(__half2*)&v0.y, *(__half2*)&v1.y),
                                 __hmax2(*(__half2*)&v2.y, *(__half2*)&v3.y)));
    }
    for (; j < cnt; j++) {
        int s = g_csr[start + j];
        uint2 v = yv[s * 32 + lane];
        m0 = __hmax2(m0, *(__half2*)&v.x);
        m1 = __hmax2(m1, *(__half2*)&v.y);
    }

    float2 f0 = __half22float2(m0);
    float2 f1 = __half22float2(m1);

    float4 xv = ((const float4*)x)[node * 32 + lane];
    float4 h;
    h.x = xv.x + f0.x; h.y = xv.y + f0.y;
    h.z = xv.z + f1.x; h.w = xv.w + f1.y;

    float ss = h.x * h.x + h.y * h.y + h.z * h.z + h.w * h.w;
#pragma unroll
    for (int d = 16; d; d >>= 1) ss += __shfl_xor_sync(0xFFFFFFFFu, ss, d);

    float inv = rsqrtf(ss * (1.0f / DD) + 1e-5f);

    float4 gv = ((const float4*)g)[lane];
    float4 rv = ((const float4*)rb)[lane];
    float4 o;
    o.x = h.x * inv * gv.x + rv.x;
    o.y = h.y * inv * gv.y + rv.y;
    o.z = h.z * inv * gv.z + rv.z;
    o.w = h.w * inv * gv.w + rv.w;
    ((float4*)out)[node * 32 + lane] = o;
}

// ---------------------------------------------------------------------------
// Launch
// ---------------------------------------------------------------------------
extern "C" void kernel_launch(void* const* d_in, const int* in_sizes, int n_in,
                              void* d_out, int out_size)
{
    const float* x  = (const float*)d_in[0];
    const int2*  e  = (const int2*) d_in[1];
    const float* W  = (const float*)d_in[2];
    const float* b  = (const float*)d_in[3];
    const float* g  = (const float*)d_in[4];
    const float* rb = (const float*)d_in[5];
    float* out = (float*)d_out;

    const int n  = in_sizes[0] / DD;   // 40000
    const int ne = in_sizes[1] / 2;    // 640000

    k_zero_deg<<<(n + 255) / 256, 256>>>(n);
    k_gemm_relu<<<n / 64, 256>>>(x, W, b);
    k_hist<<<(ne + 255) / 256, 256>>>(e, ne);
    k_off<<<(n + 255) / 256, 256>>>(n);
    k_scatter<<<(ne + 255) / 256, 256>>>(e, ne);
    k_aggregate<<<(n * 32 + 255) / 256, 256>>>(x, g, rb, out, n);
}

// round 6
// speedup vs baseline: 2.5275x; 1.1404x over previous
#include <cuda_runtime.h>
#include <cuda_fp16.h>
#include <cuda_bf16.h>

// Problem constants (fixed shapes for this problem)
#define NN 40000
#define DD 128
#define EE 640000

// Scratch (device globals; no allocation allowed)
__device__ __half g_y[NN * DD];       // relu(x @ W^T + b) per node, fp16: 10.2 MB (L2-resident)
__device__ int    g_deg[NN];
__device__ int    g_off[NN];
__device__ int    g_cur[NN];
__device__ int    g_csr[EE];
__device__ int    g_total;            // global CSR cursor

static __device__ __forceinline__ unsigned h2_bits(__half2 v) {
    return *reinterpret_cast<unsigned*>(&v);
}

// ---------------------------------------------------------------------------
// Kernel 1: zero degree counters + cursor
// ---------------------------------------------------------------------------
__global__ void k_zero_deg(int n) {
    int i = blockIdx.x * blockDim.x + threadIdx.x;
    if (i < n) g_deg[i] = 0;
    if (i == 0) g_total = 0;
}

// ---------------------------------------------------------------------------
// Kernel 2: y = relu(x @ W^T + b), output fp16.
// Packed f32x2 FFMA: each thread owns 4 row-pairs x 4 cols.
// ---------------------------------------------------------------------------
__global__ __launch_bounds__(256) void k_gemm_relu(
    const float* __restrict__ x, const float* __restrict__ W,
    const float* __restrict__ b)
{
    __shared__ float xs[32][66];     // [kk][row], stride 66: aligned LDS.64 row-pairs
    __shared__ float wt[32][132];    // [kk][col], padded

    const int t    = threadIdx.x;
    const int row0 = blockIdx.x * 64;
    const int ty   = t >> 5;         // warp id 0..7 -> rows ty*8 .. ty*8+7
    const int tx   = t & 31;         // lane -> cols tx*4 .. tx*4+3

    unsigned long long acc[4][4];    // [row pair][col], f32x2 packed
#pragma unroll
    for (int r = 0; r < 4; r++)
#pragma unroll
        for (int c = 0; c < 4; c++) acc[r][c] = 0ull;

    for (int kc = 0; kc < DD; kc += 32) {
#pragma unroll
        for (int i = t; i < 64 * 32; i += 256) {
            int r = i >> 5, kk = i & 31;
            xs[kk][r] = x[(row0 + r) * DD + kc + kk];
        }
#pragma unroll
        for (int i = t; i < 128 * 32; i += 256) {
            int c = i >> 5, kk = i & 31;
            wt[kk][c] = W[c * DD + kc + kk];
        }
        __syncthreads();

#pragma unroll
        for (int kk = 0; kk < 32; kk++) {
            float4 wv = *(const float4*)&wt[kk][tx * 4];   // conflict-free LDS.128
            unsigned long long wd[4];
            asm("mov.b64 %0, {%1, %1};" : "=l"(wd[0]) : "f"(wv.x));
            asm("mov.b64 %0, {%1, %1};" : "=l"(wd[1]) : "f"(wv.y));
            asm("mov.b64 %0, {%1, %1};" : "=l"(wd[2]) : "f"(wv.z));
            asm("mov.b64 %0, {%1, %1};" : "=l"(wd[3]) : "f"(wv.w));

            unsigned long long xp[4];                      // row-pair broadcasts (LDS.64)
#pragma unroll
            for (int r = 0; r < 4; r++)
                xp[r] = *(const unsigned long long*)&xs[kk][ty * 8 + 2 * r];

#pragma unroll
            for (int r = 0; r < 4; r++)
#pragma unroll
                for (int c = 0; c < 4; c++)
                    asm("fma.rn.f32x2 %0, %1, %2, %0;"
                        : "+l"(acc[r][c]) : "l"(xp[r]), "l"(wd[c]));
        }
        __syncthreads();
    }

    float4 bv = *(const float4*)&b[tx * 4];
#pragma unroll
    for (int r = 0; r < 4; r++) {
        float lo[4], hi[4];
#pragma unroll
        for (int c = 0; c < 4; c++) {
            unsigned int l = (unsigned int)(acc[r][c] & 0xFFFFFFFFull);
            unsigned int h = (unsigned int)(acc[r][c] >> 32);
            lo[c] = __uint_as_float(l);
            hi[c] = __uint_as_float(h);
        }
        int rowA = row0 + ty * 8 + 2 * r;      // low half
        int rowB = rowA + 1;                   // high half
        float a0 = fmaxf(lo[0] + bv.x, 0.f), a1 = fmaxf(lo[1] + bv.y, 0.f);
        float a2 = fmaxf(lo[2] + bv.z, 0.f), a3 = fmaxf(lo[3] + bv.w, 0.f);
        float b0 = fmaxf(hi[0] + bv.x, 0.f), b1 = fmaxf(hi[1] + bv.y, 0.f);
        float b2 = fmaxf(hi[2] + bv.z, 0.f), b3 = fmaxf(hi[3] + bv.w, 0.f);

        uint2 pa, pb;
        pa.x = h2_bits(__floats2half2_rn(a0, a1));
        pa.y = h2_bits(__floats2half2_rn(a2, a3));
        pb.x = h2_bits(__floats2half2_rn(b0, b1));
        pb.y = h2_bits(__floats2half2_rn(b2, b3));
        *(uint2*)&g_y[rowA * DD + tx * 4] = pa;
        *(uint2*)&g_y[rowB * DD + tx * 4] = pb;
    }
}

// ---------------------------------------------------------------------------
// Kernel 3: histogram of dst degrees (coalesced int2 edge loads)
// ---------------------------------------------------------------------------
__global__ void k_hist(const int2* __restrict__ e, int ne) {
    int i = blockIdx.x * blockDim.x + threadIdx.x;
    if (i < ne) {
        int2 p = e[i];
        atomicAdd(&g_deg[p.y], 1);
    }
}

// ---------------------------------------------------------------------------
// Kernel 4: offsets via block scan + atomic block base.
// Segment order across blocks is nondeterministic; max is order-invariant.
// ---------------------------------------------------------------------------
__global__ __launch_bounds__(256) void k_off(int n) {
    __shared__ int wsum[8];
    __shared__ int blockbase;
    const int t    = threadIdx.x;
    const int lane = t & 31, wid = t >> 5;
    const int i    = blockIdx.x * 256 + t;

    int v = (i < n) ? g_deg[i] : 0;

    int s = v;
#pragma unroll
    for (int d = 1; d < 32; d <<= 1) {
        int m = __shfl_up_sync(0xFFFFFFFFu, s, d);
        if (lane >= d) s += m;
    }
    if (lane == 31) wsum[wid] = s;
    __syncthreads();

    if (t < 8) {
        int ws = wsum[t];
        int ss = ws;
#pragma unroll
        for (int d = 1; d < 8; d <<= 1) {
            int m = __shfl_up_sync(0xFFu, ss, d);
            if (t >= d) ss += m;
        }
        wsum[t] = ss - ws;
        if (t == 7) blockbase = atomicAdd(&g_total, ss);
    }
    __syncthreads();

    if (i < n) {
        int excl = blockbase + wsum[wid] + (s - v);
        g_off[i] = excl;
        g_cur[i] = excl;
    }
}

// ---------------------------------------------------------------------------
// Kernel 5: scatter edges into dst-CSR (coalesced int2 edge loads)
// ---------------------------------------------------------------------------
__global__ void k_scatter(const int2* __restrict__ e, int ne) {
    int i = blockIdx.x * blockDim.x + threadIdx.x;
    if (i < ne) {
        int2 p = e[i];
        int pos = atomicAdd(&g_cur[p.y], 1);
        g_csr[pos] = p.x;  // src
    }
}

// ---------------------------------------------------------------------------
// Kernel 6: per-dst gather-max over fp16 y + residual + RMSNorm. Warp/node.
// ---------------------------------------------------------------------------
__global__ __launch_bounds__(256) void k_aggregate(
    const float* __restrict__ x, const float* __restrict__ g,
    const float* __restrict__ rb, float* __restrict__ out, int n)
{
    const int node = (blockIdx.x * blockDim.x + threadIdx.x) >> 5;
    const int lane = threadIdx.x & 31;
    if (node >= n) return;

    const int start = g_off[node];
    const int cnt   = g_deg[node];
    const uint2* yv = (const uint2*)g_y;   // 8B per lane per row

    __half2 m0 = __float2half2_rn(0.f);
    __half2 m1 = __float2half2_rn(0.f);

    int j = 0;
    for (; j + 4 <= cnt; j += 4) {
        int s0 = g_csr[start + j];
        int s1 = g_csr[start + j + 1];
        int s2 = g_csr[start + j + 2];
        int s3 = g_csr[start + j + 3];
        uint2 v0 = yv[s0 * 32 + lane];
        uint2 v1 = yv[s1 * 32 + lane];
        uint2 v2 = yv[s2 * 32 + lane];
        uint2 v3 = yv[s3 * 32 + lane];
        m0 = __hmax2(m0, __hmax2(__hmax2(*(__half2*)&v0.x, *(__half2*)&v1.x),
                                 __hmax2(*(__half2*)&v2.x, *(__half2*)&v3.x)));
        m1 = __hmax2(m1, __hmax2(__hmax2(*(__half2*)&v0.y, *(__half2*)&v1.y),
                                 __hmax2(*(__half2*)&v2.y, *(__half2*)&v3.y)));
    }
    for (; j < cnt; j++) {
        int s = g_csr[start + j];
        uint2 v = yv[s * 32 + lane];
        m0 = __hmax2(m0, *(__half2*)&v.x);
        m1 = __hmax2(m1, *(__half2*)&v.y);
    }

    float2 f0 = __half22float2(m0);
    float2 f1 = __half22float2(m1);

    float4 xv = ((const float4*)x)[node * 32 + lane];
    float4 h;
    h.x = xv.x + f0.x; h.y = xv.y + f0.y;
    h.z = xv.z + f1.x; h.w = xv.w + f1.y;

    float ss = h.x * h.x + h.y * h.y + h.z * h.z + h.w * h.w;
#pragma unroll
    for (int d = 16; d; d >>= 1) ss += __shfl_xor_sync(0xFFFFFFFFu, ss, d);

    float inv = rsqrtf(ss * (1.0f / DD) + 1e-5f);

    float4 gv = ((const float4*)g)[lane];
    float4 rv = ((const float4*)rb)[lane];
    float4 o;
    o.x = h.x * inv * gv.x + rv.x;
    o.y = h.y * inv * gv.y + rv.y;
    o.z = h.z * inv * gv.z + rv.z;
    o.w = h.w * inv * gv.w + rv.w;
    ((float4*)out)[node * 32 + lane] = o;
}

// ---------------------------------------------------------------------------
// Launch: fork CSR-build chain onto a second stream, concurrent with GEMM.
// Streams/events are created fresh each call (kernel_launch only runs for the
// correctness pass + the capture pass; no device memory is involved).
// ---------------------------------------------------------------------------
extern "C" void kernel_launch(void* const* d_in, const int* in_sizes, int n_in,
                              void* d_out, int out_size)
{
    const float* x  = (const float*)d_in[0];
    const int2*  e  = (const int2*) d_in[1];
    const float* W  = (const float*)d_in[2];
    const float* b  = (const float*)d_in[3];
    const float* g  = (const float*)d_in[4];
    const float* rb = (const float*)d_in[5];
    float* out = (float*)d_out;

    const int n  = in_sizes[0] / DD;   // 40000
    const int ne = in_sizes[1] / 2;    // 640000

    cudaStream_t sB;
    cudaEvent_t  eFork, eJoin;
    cudaStreamCreateWithFlags(&sB, cudaStreamNonBlocking);
    cudaEventCreateWithFlags(&eFork, cudaEventDisableTiming);
    cudaEventCreateWithFlags(&eJoin, cudaEventDisableTiming);

    // fork from the (captured) main stream
    cudaEventRecord(eFork, (cudaStream_t)0);
    cudaStreamWaitEvent(sB, eFork, 0);

    // stream B: CSR build chain (depends only on e)
    k_zero_deg<<<(n + 255) / 256, 256, 0, sB>>>(n);
    k_hist   <<<(ne + 255) / 256, 256, 0, sB>>>(e, ne);
    k_off    <<<(n + 255) / 256, 256, 0, sB>>>(n);
    k_scatter<<<(ne + 255) / 256, 256, 0, sB>>>(e, ne);
    cudaEventRecord(eJoin, sB);

    // main stream: GEMM (depends only on x, W, b) — runs concurrently
    k_gemm_relu<<<n / 64, 256>>>(x, W, b);

    // join, then aggregate
    cudaStreamWaitEvent((cudaStream_t)0, eJoin, 0);
    k_aggregate<<<(n * 32 + 255) / 256, 256>>>(x, g, rb, out, n);
}